// round 10
// baseline (speedup 1.0000x reference)
#include <cuda_runtime.h>

#define NBLK 296               // 148 SMs x 2 resident CTAs (best measured config)
#define NTHR 512
#define CHUNK 2048LL           // float4 per chunk = 32 KB

// Scratch (no allocations). State overwritten each run, wraps (g_count), or is
// monotonic with entry-captured baseline (g_epoch) -> graph-replay safe.
__device__ double                g_partials[NBLK];
__device__ float                 g_total;
__device__ unsigned int          g_count;
__device__ volatile unsigned int g_epoch;

__global__ void __launch_bounds__(NTHR, 2) fused_kernel(const float4* __restrict__ x4,
                                                        float4* __restrict__ out4,
                                                        long long n4)
{
    const long long nch     = n4 / CHUNK;          // 8192 for 8192^2
    const long long n4_main = nch * CHUNK;
    const long long tid     = (long long)blockIdx.x * blockDim.x + threadIdx.x;
    const long long gstride = (long long)gridDim.x * blockDim.x;

    // Capture epoch BEFORE any work: bumper fires only after all CTAs arrive.
    const unsigned epoch0 = g_epoch;

    // -------- Phase 1: reduction, chunks walked DESCENDING ------------------
    // Loads feed only accumulators -> consecutive iterations' loads are
    // independent; already at the read-only throughput cap (~5.9 TB/s).
    float s0=0.f, s1=0.f, s2=0.f, s3=0.f;

    for (long long c = nch - 1 - blockIdx.x; c >= 0; c -= NBLK) {
        const float4* base = x4 + c * CHUNK + threadIdx.x;
        float4 v0 = base[0];
        float4 v1 = base[512];
        float4 v2 = base[1024];
        float4 v3 = base[1536];
        s0 += (v0.x + v0.y) + (v0.z + v0.w);
        s1 += (v1.x + v1.y) + (v1.z + v1.w);
        s2 += (v2.x + v2.y) + (v2.z + v2.w);
        s3 += (v3.x + v3.y) + (v3.z + v3.w);
    }
    for (long long i = n4_main + tid; i < n4; i += gstride) {   // tail (empty here)
        float4 v = x4[i];
        s0 += (v.x + v.y) + (v.z + v.w);
    }

    double acc = ((double)s0 + (double)s1) + ((double)s2 + (double)s3);

    __shared__ double sdata[NTHR];
    sdata[threadIdx.x] = acc;
    __syncthreads();
    for (int s = NTHR/2; s > 0; s >>= 1) {
        if (threadIdx.x < s) sdata[threadIdx.x] += sdata[threadIdx.x + s];
        __syncthreads();
    }

    // -------- Arrival + last-block finalize ---------------------------------
    __shared__ bool s_isLast;
    if (threadIdx.x == 0) {
        g_partials[blockIdx.x] = sdata[0];
        __threadfence();
        unsigned v = atomicInc(&g_count, gridDim.x - 1);   // wraps -> replay-safe
        s_isLast = (v == gridDim.x - 1);
    }
    __syncthreads();

    if (s_isLast) {
        double facc = 0.0;
        for (int k = threadIdx.x; k < NBLK; k += NTHR) facc += g_partials[k];
        sdata[threadIdx.x] = facc;
        __syncthreads();
        for (int s = NTHR/2; s > 0; s >>= 1) {
            if (threadIdx.x < s) sdata[threadIdx.x] += sdata[threadIdx.x + s];
            __syncthreads();
        }
        if (threadIdx.x == 0) {
            float  sf = (float)sdata[0];        // mimic jnp.sum's fp32 result
            double nn = trunc((double)sf);
            double tt = (nn > 1.0) ? nn * (nn - 1.0) * 0.5 : 0.0;
            g_total = (float)tt;
            __threadfence();
            g_epoch = g_epoch + 1;              // release
        }
        __syncthreads();
    } else {
        if (threadIdx.x == 0) {
            while (g_epoch == epoch0) { __nanosleep(64); }
            __threadfence();
        }
        __syncthreads();
    }

    __shared__ float s_t;
    if (threadIdx.x == 0) s_t = g_total;
    __syncthreads();
    const float t = s_t;

    // -------- Phase 2: out = x + t, ASCENDING, SOFTWARE-PIPELINED -----------
    // Double-buffered: issue chunk c+NBLK's 4 loads BEFORE storing chunk c,
    // so each warp keeps 4 LDG.128 in flight across the store phase instead
    // of draining to zero every iteration. First chunks hit the low-address
    // L2 residue phase 1 just left. __stcs/__ldcs avoid polluting it.
    {
        long long c = blockIdx.x;
        if (c < nch) {
            const float4* src = x4 + c * CHUNK + threadIdx.x;
            float4 p0 = __ldcs(src);
            float4 p1 = __ldcs(src + 512);
            float4 p2 = __ldcs(src + 1024);
            float4 p3 = __ldcs(src + 1536);
            while (true) {
                const long long cn = c + NBLK;
                float4 q0, q1, q2, q3;
                const bool have_next = (cn < nch);
                if (have_next) {
                    const float4* srcn = x4 + cn * CHUNK + threadIdx.x;
                    q0 = __ldcs(srcn);            // prefetch next chunk first
                    q1 = __ldcs(srcn + 512);
                    q2 = __ldcs(srcn + 1024);
                    q3 = __ldcs(srcn + 1536);
                }
                float4* dst = out4 + c * CHUNK + threadIdx.x;
                p0.x += t; p0.y += t; p0.z += t; p0.w += t;
                p1.x += t; p1.y += t; p1.z += t; p1.w += t;
                p2.x += t; p2.y += t; p2.z += t; p2.w += t;
                p3.x += t; p3.y += t; p3.z += t; p3.w += t;
                __stcs(dst,        p0);
                __stcs(dst + 512,  p1);
                __stcs(dst + 1024, p2);
                __stcs(dst + 1536, p3);
                if (!have_next) break;
                p0 = q0; p1 = q1; p2 = q2; p3 = q3;
                c = cn;
            }
        }
    }
    for (long long i = n4_main + tid; i < n4; i += gstride) {   // tail (empty here)
        float4 v = __ldcs(&x4[i]);
        v.x += t; v.y += t; v.z += t; v.w += t;
        __stcs(&out4[i], v);
    }
}

extern "C" void kernel_launch(void* const* d_in, const int* in_sizes, int n_in,
                              void* d_out, int out_size)
{
    const float4* x4   = (const float4*)d_in[0];
    float4*       out4 = (float4*)d_out;
    long long n  = (long long)in_sizes[0];   // 8192*8192
    long long n4 = n >> 2;

    fused_kernel<<<NBLK, NTHR>>>(x4, out4, n4);
}